// round 16
// baseline (speedup 1.0000x reference)
#include <cuda_runtime.h>
#include <cuda_fp16.h>
#include <math.h>
#include <stdint.h>

#define SEQ    2048
#define NROWS  4096
#define NHEADS 16

// ---------------- fp16 planes ----------------
__device__ __half g_xh [NROWS * 2048];
__device__ __half g_q1h[NROWS * 512];
__device__ __half g_ckvh[NROWS * 576];
__device__ __half g_qh [NROWS * 3072];
__device__ __half g_kvh[NROWS * 4096];
__device__ __half g_peh[NROWS * 64];
__device__ __half g_ah [NROWS * 2048];
__device__ __half g_Wqah[2048 * 512];
__device__ __half g_Wqbh[512 * 3072];
__device__ __half g_Wkvah[2048 * 576];
__device__ __half g_Wkvbh[512 * 4096];
__device__ __half g_Wouth[2048 * 2048];

// ================= helpers =================
__device__ __forceinline__ uint32_t smem_u32(const void* p) {
    uint32_t a;
    asm("{ .reg .u64 t; cvta.to.shared.u64 t, %1; cvt.u32.u64 %0, t; }" : "=r"(a) : "l"(p));
    return a;
}
__device__ __forceinline__ void ldsm4(uint32_t& r0, uint32_t& r1, uint32_t& r2, uint32_t& r3,
                                      uint32_t addr) {
    asm volatile("ldmatrix.sync.aligned.m8n8.x4.shared.b16 {%0,%1,%2,%3}, [%4];"
                 : "=r"(r0), "=r"(r1), "=r"(r2), "=r"(r3) : "r"(addr));
}
__device__ __forceinline__ void ldsm4t(uint32_t& r0, uint32_t& r1, uint32_t& r2, uint32_t& r3,
                                       uint32_t addr) {
    asm volatile("ldmatrix.sync.aligned.m8n8.x4.trans.shared.b16 {%0,%1,%2,%3}, [%4];"
                 : "=r"(r0), "=r"(r1), "=r"(r2), "=r"(r3) : "r"(addr));
}
__device__ __forceinline__ void mma16816(float* c, const uint32_t* a, const uint32_t* b) {
    asm volatile(
        "mma.sync.aligned.m16n8k16.row.col.f32.f16.f16.f32 "
        "{%0,%1,%2,%3}, {%4,%5,%6,%7}, {%8,%9}, {%0,%1,%2,%3};"
        : "+f"(c[0]), "+f"(c[1]), "+f"(c[2]), "+f"(c[3])
        : "r"(a[0]), "r"(a[1]), "r"(a[2]), "r"(a[3]), "r"(b[0]), "r"(b[1]));
}
__device__ __forceinline__ void cp16(uint32_t saddr, const void* g) {
    asm volatile("cp.async.ca.shared.global [%0], [%1], 16;" :: "r"(saddr), "l"(g));
}
#define CP_COMMIT() asm volatile("cp.async.commit_group;" ::: "memory")
#define CP_WAIT(n)  asm volatile("cp.async.wait_group %0;" :: "n"(n) : "memory")

__device__ __forceinline__ uint32_t pack_h2(float a, float b) {
    __half2 t = __floats2half2_rn(a, b);
    return *reinterpret_cast<uint32_t*>(&t);
}

// ---------------- input conversion ----------------
__global__ void conv_h(const float* __restrict__ in, __half* __restrict__ out, int n4)
{
    int i = blockIdx.x * blockDim.x + threadIdx.x;
    if (i < n4) {
        float4 v = reinterpret_cast<const float4*>(in)[i];
        uint2 o;
        o.x = pack_h2(v.x, v.y);
        o.y = pack_h2(v.z, v.w);
        reinterpret_cast<uint2*>(out)[i] = o;
    }
}

// ================= HMMA fp16 GEMM, 3-stage pipeline =================
#define KCH 32
#define ALD 40
#define A_PLANE (128 * ALD)

template<int NTILE>
__global__ __launch_bounds__(256) void gemm_hmma(
    const __half* __restrict__ A, int lda,
    const __half* __restrict__ B, int ldb,
    float* __restrict__ Cf, int ldc,
    __half* __restrict__ Ch, int ldh,
    int nchunks)
{
    constexpr int BLD = NTILE + 8;
    constexpr int B_PLANE = KCH * BLD;
    constexpr int STAGE_E = A_PLANE + B_PLANE;
    constexpr int NI = NTILE / 16;
    constexpr int BSEG = NTILE / 64;

    extern __shared__ __half sm[];
    const int tid  = threadIdx.x;
    const int wid  = tid >> 5;
    const int lane = tid & 31;
    const int m0 = blockIdx.y * 128;
    const int n0 = blockIdx.x * NTILE;
    const int mw = (wid & 3) * 32;
    const int nw = (wid >> 2) * (NTILE / 2);
    const uint32_t sm_base = smem_u32(sm);

    float acc[2][NI][4];
    #pragma unroll
    for (int i = 0; i < 2; i++)
        #pragma unroll
        for (int j = 0; j < NI; j++)
            #pragma unroll
            for (int e = 0; e < 4; e++) acc[i][j][e] = 0.f;

    const int ar  = tid >> 1;
    const int as  = (tid & 1) * 2;

    const uint32_t aRow = lane & 15;
    const uint32_t aCol = (lane >> 4) * 8;
    const uint32_t aOff = (uint32_t)((mw + aRow) * ALD + aCol) * 2;
    const uint32_t bOff = (uint32_t)(A_PLANE + (lane & 15) * BLD + nw + (lane >> 4) * 8) * 2;

    auto load_stage = [&](int stg, int ch) {
        const uint32_t sb = sm_base + (uint32_t)stg * (STAGE_E * 2);
        const int k0 = ch * KCH;
        #pragma unroll
        for (int s = 0; s < 2; s++) {
            int seg = as + s;
            cp16(sb + (uint32_t)(ar * ALD + seg * 8) * 2,
                 A + (size_t)(m0 + ar) * lda + k0 + seg * 8);
        }
        #pragma unroll
        for (int s = 0; s < BSEG; s++) {
            int idx = tid * BSEG + s;
            int row = idx / (NTILE / 8);
            int seg = idx % (NTILE / 8);
            cp16(sb + (uint32_t)(A_PLANE + row * BLD + seg * 8) * 2,
                 B + (size_t)(k0 + row) * ldb + n0 + seg * 8);
        }
    };

    load_stage(0, 0); CP_COMMIT();
    load_stage(1, 1); CP_COMMIT();

    for (int ch = 0; ch < nchunks; ch++) {
        const int stg = ch % 3;
        if (ch + 2 < nchunks) {
            load_stage((ch + 2) % 3, ch + 2);
            CP_COMMIT();
            CP_WAIT(2);
        } else if (ch + 1 < nchunks) {
            CP_WAIT(1);
        } else {
            CP_WAIT(0);
        }
        __syncthreads();

        const uint32_t sb = sm_base + (uint32_t)stg * (STAGE_E * 2);
        #pragma unroll
        for (int ks = 0; ks < 2; ks++) {
            const uint32_t kA = (uint32_t)(ks * 16) * 2;
            const uint32_t kB = (uint32_t)(ks * 16 * BLD) * 2;
            uint32_t a[2][4], b[NI][2];
            #pragma unroll
            for (int mi = 0; mi < 2; mi++) {
                uint32_t off = (uint32_t)(mi * 16 * ALD) * 2 + kA;
                ldsm4(a[mi][0], a[mi][1], a[mi][2], a[mi][3], sb + aOff + off);
            }
            #pragma unroll
            for (int np = 0; np < NI / 2; np++) {
                uint32_t off = kB + (uint32_t)(np * 16) * 2;
                ldsm4t(b[np * 2][0], b[np * 2][1], b[np * 2 + 1][0], b[np * 2 + 1][1],
                       sb + bOff + off);
            }
            #pragma unroll
            for (int mi = 0; mi < 2; mi++)
                #pragma unroll
                for (int ni = 0; ni < NI; ni++)
                    mma16816(acc[mi][ni], a[mi], b[ni]);
        }
        __syncthreads();
    }

    const int cr = lane >> 2;
    const int cc = (lane & 3) * 2;
    #pragma unroll
    for (int mi = 0; mi < 2; mi++)
        #pragma unroll
        for (int ni = 0; ni < NI; ni++) {
            int row = m0 + mw + mi * 16 + cr;
            int col = n0 + nw + ni * 8 + cc;
            if (Cf) {
                *reinterpret_cast<float2*>(Cf + (size_t)row * ldc + col) =
                    make_float2(acc[mi][ni][0], acc[mi][ni][1]);
                *reinterpret_cast<float2*>(Cf + (size_t)(row + 8) * ldc + col) =
                    make_float2(acc[mi][ni][2], acc[mi][ni][3]);
            }
            if (Ch) {
                *reinterpret_cast<uint32_t*>(Ch + (size_t)row * ldh + col) =
                    pack_h2(acc[mi][ni][0], acc[mi][ni][1]);
                *reinterpret_cast<uint32_t*>(Ch + (size_t)(row + 8) * ldh + col) =
                    pack_h2(acc[mi][ni][2], acc[mi][ni][3]);
            }
        }
}

#define GEMM_SMEM_128 (3 * (A_PLANE + KCH * 136) * 2)
#define GEMM_SMEM_64  (3 * (A_PLANE + KCH * 72) * 2)

// ---------------- RoPE ----------------
__global__ void rope_kernel()
{
    const int row  = blockIdx.x;
    const int pos  = row & (SEQ - 1);
    const int warp = threadIdx.x >> 5;
    const int lane = threadIdx.x & 31;

    float theta = __powf(10000.0f, -(float)lane * (1.0f / 32.0f));
    float ang = (float)pos * theta;
    float s, c;
    sincosf(ang, &s, &c);

    if (warp < 16) {
        size_t off = (size_t)row * 3072 + warp * 192 + 128 + 2 * lane;
        uint32_t hv = *reinterpret_cast<uint32_t*>(g_qh + off);
        __half2 h2 = *reinterpret_cast<__half2*>(&hv);
        float x1 = __half2float(h2.x);
        float x2 = __half2float(h2.y);
        *reinterpret_cast<uint32_t*>(g_qh + off) =
            pack_h2(x1 * c - x2 * s, x1 * s + x2 * c);
    } else {
        size_t off = (size_t)row * 576 + 512 + 2 * lane;
        uint32_t hv = *reinterpret_cast<uint32_t*>(g_ckvh + off);
        __half2 h2 = *reinterpret_cast<__half2*>(&hv);
        float x1 = __half2float(h2.x);
        float x2 = __half2float(h2.y);
        *reinterpret_cast<uint32_t*>(g_peh + (size_t)row * 64 + 2 * lane) =
            pack_h2(x1 * c - x2 * s, x1 * s + x2 * c);
    }
}

// ================= HMMA fp16 flash attention, KT=64, 3-stage =================
#define QT 128
#define KT 64
#define QLD 200
#define KLD 200
#define VLD 136
#define AQ 0
#define AK (QT * QLD)                        // 25600
#define K_STG (KT * KLD)                     // 12800
#define AV (AK + 3 * K_STG)                  // 64000
#define V_STG (KT * VLD)                     // 8704
#define ATT_E (AV + 3 * V_STG)               // 90112 elems
#define ATT_SMEM (ATT_E * 2)                 // 180224 bytes

__global__ __launch_bounds__(256, 1) void attn_hmma()
{
    extern __shared__ __half sm[];
    const int tid = threadIdx.x, wid = tid >> 5, lane = tid & 31;
    const int b = blockIdx.z, h = blockIdx.y;
    const int q0 = blockIdx.x * QT;
    const uint32_t sb = smem_u32(sm);
    const float scale = 0.07216878364870323f;   // 1/sqrt(192)

    // ---- async load Q tile [128][192] ----
    {
        int r = tid >> 1;
        const __half* src = g_qh + (size_t)(b * SEQ + q0 + r) * 3072 + h * 192;
        uint32_t dst = sb + (uint32_t)(AQ + r * QLD) * 2;
        #pragma unroll
        for (int s = 0; s < 12; s++) {
            int seg = (tid & 1) * 12 + s;
            cp16(dst + seg * 16, src + seg * 8);
        }
    }

    auto load_kv = [&](int stg, int kt0) {
        int r = tid >> 2;
        size_t row = (size_t)(b * SEQ + kt0 + r);
        const __half* kn = g_kvh + row * 4096 + h * 256;
        const __half* pe = g_peh + row * 64;
        uint32_t kd = sb + (uint32_t)(AK + stg * K_STG + r * KLD) * 2;
        uint32_t vd = sb + (uint32_t)(AV + stg * V_STG + r * VLD) * 2;
        #pragma unroll
        for (int s = 0; s < 10; s++) {
            int seg = (tid & 3) * 10 + s;
            if (seg < 16)      cp16(kd + seg * 16, kn + seg * 8);
            else if (seg < 24) cp16(kd + seg * 16, pe + (seg - 16) * 8);
            else               cp16(vd + (seg - 24) * 16, kn + 128 + (seg - 24) * 8);
        }
    };

    const int ntiles = q0 / KT + QT / KT;
    load_kv(0, 0); CP_COMMIT();
    load_kv(1, KT); CP_COMMIT();

    float m0 = -INFINITY, m1 = -INFINITY, l0 = 0.f, l1 = 0.f;
    float O[16][4];
    #pragma unroll
    for (int od = 0; od < 16; od++)
        #pragma unroll
        for (int e = 0; e < 4; e++) O[od][e] = 0.f;

    const uint32_t qb = sb + (uint32_t)(AQ + (wid * 16 + (lane & 15)) * QLD + (lane >> 4) * 8) * 2;

    for (int t = 0; t < ntiles; t++) {
        const int stg = t % 3;
        if (t + 2 < ntiles) {
            load_kv((t + 2) % 3, (t + 2) * KT);
            CP_COMMIT();
            CP_WAIT(2);
        } else if (t + 1 < ntiles) {
            CP_WAIT(1);
        } else {
            CP_WAIT(0);
        }
        __syncthreads();

        // ---- S = Q K^T ----
        float S[8][4];
        #pragma unroll
        for (int g = 0; g < 8; g++)
            #pragma unroll
            for (int e = 0; e < 4; e++) S[g][e] = 0.f;

        const uint32_t kb = sb + (uint32_t)(AK + stg * K_STG + (lane & 15) * KLD + (lane >> 4) * 8) * 2;
        #pragma unroll
        for (int ks = 0; ks < 12; ks++) {
            uint32_t a[4];
            ldsm4(a[0], a[1], a[2], a[3], qb + ks * 32);
            #pragma unroll
            for (int np = 0; np < 4; np++) {
                uint32_t off = (uint32_t)(np * 16 * KLD) * 2 + ks * 32;
                uint32_t h0, h1, h2, h3;
                ldsm4(h0, h1, h2, h3, kb + off);
                uint32_t b0[2] = {h0, h2}, b1[2] = {h1, h3};
                mma16816(S[np * 2],     a, b0);
                mma16816(S[np * 2 + 1], a, b1);
            }
        }

        // ---- scale + causal mask ----
        const int mrow0 = q0 + wid * 16 + (lane >> 2);
        const int kcol0 = t * KT + (lane & 3) * 2;
        const bool needmask = (t * KT + KT - 1) > (q0 + wid * 16);
        if (needmask) {
            #pragma unroll
            for (int g = 0; g < 8; g++) {
                int kc = kcol0 + g * 8;
                S[g][0] = (kc     <= mrow0)     ? S[g][0] * scale : -INFINITY;
                S[g][1] = (kc + 1 <= mrow0)     ? S[g][1] * scale : -INFINITY;
                S[g][2] = (kc     <= mrow0 + 8) ? S[g][2] * scale : -INFINITY;
                S[g][3] = (kc + 1 <= mrow0 + 8) ? S[g][3] * scale : -INFINITY;
            }
        } else {
            #pragma unroll
            for (int g = 0; g < 8; g++)
                #pragma unroll
                for (int e = 0; e < 4; e++) S[g][e] *= scale;
        }

        // ---- online softmax ----
        float tm0 = -INFINITY, tm1 = -INFINITY;
        #pragma unroll
        for (int g = 0; g < 8; g++) {
            tm0 = fmaxf(tm0, fmaxf(S[g][0], S[g][1]));
            tm1 = fmaxf(tm1, fmaxf(S[g][2], S[g][3]));
        }
        tm0 = fmaxf(tm0, __shfl_xor_sync(0xffffffffu, tm0, 1));
        tm0 = fmaxf(tm0, __shfl_xor_sync(0xffffffffu, tm0, 2));
        tm1 = fmaxf(tm1, __shfl_xor_sync(0xffffffffu, tm1, 1));
        tm1 = fmaxf(tm1, __shfl_xor_sync(0xffffffffu, tm1, 2));

        float mn0 = fmaxf(m0, tm0), mn1 = fmaxf(m1, tm1);
        float al0 = __expf(m0 - mn0), al1 = __expf(m1 - mn1);
        m0 = mn0; m1 = mn1;

        float P[8][4];
        float s0 = 0.f, s1 = 0.f;
        #pragma unroll
        for (int g = 0; g < 8; g++) {
            P[g][0] = __expf(S[g][0] - m0); s0 += P[g][0];
            P[g][1] = __expf(S[g][1] - m0); s0 += P[g][1];
            P[g][2] = __expf(S[g][2] - m1); s1 += P[g][2];
            P[g][3] = __expf(S[g][3] - m1); s1 += P[g][3];
        }
        s0 += __shfl_xor_sync(0xffffffffu, s0, 1);
        s0 += __shfl_xor_sync(0xffffffffu, s0, 2);
        s1 += __shfl_xor_sync(0xffffffffu, s1, 1);
        s1 += __shfl_xor_sync(0xffffffffu, s1, 2);
        l0 = l0 * al0 + s0;
        l1 = l1 * al1 + s1;

        #pragma unroll
        for (int od = 0; od < 16; od++) {
            O[od][0] *= al0; O[od][1] *= al0;
            O[od][2] *= al1; O[od][3] *= al1;
        }

        // ---- P -> fp16 a-frags ----
        uint32_t aP[4][4];
        #pragma unroll
        for (int kp = 0; kp < 4; kp++) {
            #pragma unroll
            for (int rr = 0; rr < 2; rr++) {
                #pragma unroll
                for (int hh = 0; hh < 2; hh++) {
                    aP[kp][hh * 2 + rr] = pack_h2(P[2 * kp + hh][rr * 2 + 0],
                                                  P[2 * kp + hh][rr * 2 + 1]);
                }
            }
        }

        // ---- O += P V ----
        const uint32_t vb = sb + (uint32_t)(AV + stg * V_STG + (lane & 15) * VLD + (lane >> 4) * 8) * 2;
        #pragma unroll
        for (int kp = 0; kp < 4; kp++) {
            const uint32_t vk = vb + (uint32_t)(kp * 16 * VLD) * 2;
            #pragma unroll
            for (int od2 = 0; od2 < 8; od2++) {
                uint32_t bv[4];
                ldsm4t(bv[0], bv[1], bv[2], bv[3], vk + od2 * 32);
                mma16816(O[od2 * 2],     aP[kp], bv);
                mma16816(O[od2 * 2 + 1], aP[kp], bv + 2);
            }
        }
        __syncthreads();
    }

    // ---- normalize + fp16 write ----
    float inv0 = 1.f / l0, inv1 = 1.f / l1;
    int row0 = b * SEQ + q0 + wid * 16 + (lane >> 2);
    size_t o0 = (size_t)row0 * 2048 + h * 128 + (lane & 3) * 2;
    size_t o1 = (size_t)(row0 + 8) * 2048 + h * 128 + (lane & 3) * 2;
    #pragma unroll
    for (int od = 0; od < 16; od++) {
        *reinterpret_cast<uint32_t*>(g_ah + o0 + od * 8) =
            pack_h2(O[od][0] * inv0, O[od][1] * inv0);
        *reinterpret_cast<uint32_t*>(g_ah + o1 + od * 8) =
            pack_h2(O[od][2] * inv1, O[od][3] * inv1);
    }
}

// ---------------- launch ----------------
static inline void conv_on(cudaStream_t st, const float* in, __half* out, int nelem)
{
    int n4 = nelem / 4;
    conv_h<<<(n4 + 255) / 256, 256, 0, st>>>(in, out, n4);
}

extern "C" void kernel_launch(void* const* d_in, const int* in_sizes, int n_in,
                              void* d_out, int out_size)
{
    const float* x    = (const float*)d_in[0];
    const float* Wqa  = (const float*)d_in[1];
    const float* Wqb  = (const float*)d_in[2];
    const float* Wkva = (const float*)d_in[3];
    const float* Wkvb = (const float*)d_in[4];
    const float* Wout = (const float*)d_in[5];
    float* out = (float*)d_out;

    __half *xh, *q1h, *ckvh, *qh, *kvh, *ah;
    __half *wqah, *wqbh, *wkvah, *wkvbh, *wouth;
    cudaGetSymbolAddress((void**)&xh,   g_xh);
    cudaGetSymbolAddress((void**)&q1h,  g_q1h);
    cudaGetSymbolAddress((void**)&ckvh, g_ckvh);
    cudaGetSymbolAddress((void**)&qh,   g_qh);
    cudaGetSymbolAddress((void**)&kvh,  g_kvh);
    cudaGetSymbolAddress((void**)&ah,   g_ah);
    cudaGetSymbolAddress((void**)&wqah, g_Wqah);
    cudaGetSymbolAddress((void**)&wqbh, g_Wqbh);
    cudaGetSymbolAddress((void**)&wkvah, g_Wkvah);
    cudaGetSymbolAddress((void**)&wkvbh, g_Wkvbh);
    cudaGetSymbolAddress((void**)&wouth, g_Wouth);

    static cudaStream_t sA = nullptr;
    static cudaEvent_t eConv = nullptr, eQ = nullptr;
    if (!sA) {
        cudaStreamCreateWithFlags(&sA, cudaStreamNonBlocking);
        cudaEventCreateWithFlags(&eConv, cudaEventDisableTiming);
        cudaEventCreateWithFlags(&eQ,    cudaEventDisableTiming);
        cudaFuncSetAttribute(gemm_hmma<128>,
                             cudaFuncAttributeMaxDynamicSharedMemorySize, GEMM_SMEM_128);
        cudaFuncSetAttribute(gemm_hmma<64>,
                             cudaFuncAttributeMaxDynamicSharedMemorySize, GEMM_SMEM_64);
        cudaFuncSetAttribute(attn_hmma,
                             cudaFuncAttributeMaxDynamicSharedMemorySize, ATT_SMEM);
    }

    dim3 t(256);

    // ---- legacy stream: x conversion, then fork ----
    conv_on(0, x, xh, NROWS * 2048);
    cudaEventRecord(eConv, 0);

    // ---- stream A: q chain (Wqa/Wqb conv -> q1 -> q) ----
    cudaStreamWaitEvent(sA, eConv, 0);
    conv_on(sA, Wqa, wqah, 2048 * 512);
    conv_on(sA, Wqb, wqbh, 512 * 3072);
    gemm_hmma<128><<<dim3(4, 32),  t, GEMM_SMEM_128, sA>>>(xh, 2048, wqah, 512,
                                                           nullptr, 0, q1h, 512, 64);
    gemm_hmma<128><<<dim3(24, 32), t, GEMM_SMEM_128, sA>>>(q1h, 512, wqbh, 3072,
                                                           nullptr, 0, qh, 3072, 16);
    cudaEventRecord(eQ, sA);

    // ---- legacy stream: ckv chain ----
    conv_on(0, Wkva, wkvah, 2048 * 576);
    conv_on(0, Wkvb, wkvbh, 512 * 4096);
    conv_on(0, Wout, wouth, 2048 * 2048);
    gemm_hmma<128><<<dim3(4, 32), t, GEMM_SMEM_128>>>(xh, 2048, wkvah, 576,
                                                      nullptr, 0, ckvh, 576, 64);
    gemm_hmma<64><<<dim3(1, 32),  t, GEMM_SMEM_64>>>(xh, 2048, wkvah + 512, 576,
                                                     nullptr, 0, ckvh + 512, 576, 64);
    gemm_hmma<128><<<dim3(32, 32), t, GEMM_SMEM_128>>>(ckvh, 576, wkvbh, 4096,
                                                       nullptr, 0, kvh, 4096, 16);
    // join q chain, then rope (touches qh + ckvh pe cols)
    cudaStreamWaitEvent(0, eQ, 0);
    rope_kernel<<<4096, 544>>>();
    // attention + output
    attn_hmma<<<dim3(SEQ / QT, NHEADS, 2), 256, ATT_SMEM>>>();
    gemm_hmma<128><<<dim3(16, 32), t, GEMM_SMEM_128>>>(ah, 2048, wouth, 2048,
                                                       out, 2048, nullptr, 0, 64);
}

// round 17
// speedup vs baseline: 1.0616x; 1.0616x over previous
#include <cuda_runtime.h>
#include <cuda_fp16.h>
#include <math.h>
#include <stdint.h>

#define SEQ    2048
#define NROWS  4096
#define NHEADS 16

// ---------------- fp16 planes ----------------
__device__ __half g_xh [NROWS * 2048];
__device__ __half g_q1h[NROWS * 512];
__device__ __half g_ckvh[NROWS * 576];
__device__ __half g_qh [NROWS * 3072];
__device__ __half g_kvh[NROWS * 4096];
__device__ __half g_peh[NROWS * 64];
__device__ __half g_ah [NROWS * 2048];
__device__ __half g_Wqah[2048 * 512];
__device__ __half g_Wqbh[512 * 3072];
__device__ __half g_Wkvah[2048 * 576];
__device__ __half g_Wkvbh[512 * 4096];
__device__ __half g_Wouth[2048 * 2048];

// ================= helpers =================
__device__ __forceinline__ uint32_t smem_u32(const void* p) {
    uint32_t a;
    asm("{ .reg .u64 t; cvta.to.shared.u64 t, %1; cvt.u32.u64 %0, t; }" : "=r"(a) : "l"(p));
    return a;
}
__device__ __forceinline__ void ldsm4(uint32_t& r0, uint32_t& r1, uint32_t& r2, uint32_t& r3,
                                      uint32_t addr) {
    asm volatile("ldmatrix.sync.aligned.m8n8.x4.shared.b16 {%0,%1,%2,%3}, [%4];"
                 : "=r"(r0), "=r"(r1), "=r"(r2), "=r"(r3) : "r"(addr));
}
__device__ __forceinline__ void ldsm4t(uint32_t& r0, uint32_t& r1, uint32_t& r2, uint32_t& r3,
                                       uint32_t addr) {
    asm volatile("ldmatrix.sync.aligned.m8n8.x4.trans.shared.b16 {%0,%1,%2,%3}, [%4];"
                 : "=r"(r0), "=r"(r1), "=r"(r2), "=r"(r3) : "r"(addr));
}
__device__ __forceinline__ void mma16816(float* c, const uint32_t* a, const uint32_t* b) {
    asm volatile(
        "mma.sync.aligned.m16n8k16.row.col.f32.f16.f16.f32 "
        "{%0,%1,%2,%3}, {%4,%5,%6,%7}, {%8,%9}, {%0,%1,%2,%3};"
        : "+f"(c[0]), "+f"(c[1]), "+f"(c[2]), "+f"(c[3])
        : "r"(a[0]), "r"(a[1]), "r"(a[2]), "r"(a[3]), "r"(b[0]), "r"(b[1]));
}
__device__ __forceinline__ void cp16(uint32_t saddr, const void* g) {
    asm volatile("cp.async.ca.shared.global [%0], [%1], 16;" :: "r"(saddr), "l"(g));
}
#define CP_COMMIT() asm volatile("cp.async.commit_group;" ::: "memory")
#define CP_WAIT(n)  asm volatile("cp.async.wait_group %0;" :: "n"(n) : "memory")

__device__ __forceinline__ uint32_t pack_h2(float a, float b) {
    __half2 t = __floats2half2_rn(a, b);
    return *reinterpret_cast<uint32_t*>(&t);
}

// ---------------- fused input conversion (6 tensors, one launch) ----------------
#define N4_X    (NROWS * 2048 / 4)
#define N4_WQA  (2048 * 512 / 4)
#define N4_WQB  (512 * 3072 / 4)
#define N4_WKVA (2048 * 576 / 4)
#define N4_WKVB (512 * 4096 / 4)
#define N4_WOUT (2048 * 2048 / 4)
#define C0 0
#define C1 (C0 + N4_X)
#define C2 (C1 + N4_WQA)
#define C3 (C2 + N4_WQB)
#define C4 (C3 + N4_WKVA)
#define C5 (C4 + N4_WKVB)
#define C6 (C5 + N4_WOUT)

__global__ void conv6(const float* __restrict__ x,   const float* __restrict__ wqa,
                      const float* __restrict__ wqb, const float* __restrict__ wkva,
                      const float* __restrict__ wkvb, const float* __restrict__ wout)
{
    int i = blockIdx.x * blockDim.x + threadIdx.x;
    if (i >= C6) return;
    const float* src; __half* dst; int off;
    if (i < C1)      { src = x;    dst = g_xh;    off = i - C0; }
    else if (i < C2) { src = wqa;  dst = g_Wqah;  off = i - C1; }
    else if (i < C3) { src = wqb;  dst = g_Wqbh;  off = i - C2; }
    else if (i < C4) { src = wkva; dst = g_Wkvah; off = i - C3; }
    else if (i < C5) { src = wkvb; dst = g_Wkvbh; off = i - C4; }
    else             { src = wout; dst = g_Wouth; off = i - C5; }
    float4 v = reinterpret_cast<const float4*>(src)[off];
    uint2 o;
    o.x = pack_h2(v.x, v.y);
    o.y = pack_h2(v.z, v.w);
    reinterpret_cast<uint2*>(dst)[off] = o;
}

// ================= HMMA fp16 GEMM, 3-stage, templated M/N tiles =================
#define KCH 32
#define ALD 40

template<int MTILE, int NTILE>
__global__ __launch_bounds__(256) void gemm_hmma(
    const __half* __restrict__ A, int lda,
    const __half* __restrict__ B, int ldb,
    float* __restrict__ Cf, int ldc,
    __half* __restrict__ Ch, int ldh,
    int nchunks)
{
    constexpr int A_PL = MTILE * ALD;
    constexpr int BLD = NTILE + 8;
    constexpr int B_PLANE = KCH * BLD;
    constexpr int STAGE_E = A_PL + B_PLANE;
    constexpr int WM = MTILE / 32;            // warp rows
    constexpr int WN = 8 / WM;                // warp cols
    constexpr int NI = NTILE / WN / 8;        // n-frags per warp
    constexpr int BSEG = NTILE / 64;          // B cp16 per thread
    constexpr int ASEG = MTILE / 64;          // A cp16 per thread

    extern __shared__ __half sm[];
    const int tid  = threadIdx.x;
    const int wid  = tid >> 5;
    const int lane = tid & 31;
    const int m0 = blockIdx.y * MTILE;
    const int n0 = blockIdx.x * NTILE;
    const int mw = (wid % WM) * 32;
    const int nw = (wid / WM) * (NTILE / WN);
    const uint32_t sm_base = smem_u32(sm);

    float acc[2][NI][4];
    #pragma unroll
    for (int i = 0; i < 2; i++)
        #pragma unroll
        for (int j = 0; j < NI; j++)
            #pragma unroll
            for (int e = 0; e < 4; e++) acc[i][j][e] = 0.f;

    const uint32_t aRow = lane & 15;
    const uint32_t aCol = (lane >> 4) * 8;
    const uint32_t aOff = (uint32_t)((mw + aRow) * ALD + aCol) * 2;
    const uint32_t bOff = (uint32_t)(A_PL + (lane & 15) * BLD + nw + (lane >> 4) * 8) * 2;

    auto load_stage = [&](int stg, int ch) {
        const uint32_t sb = sm_base + (uint32_t)stg * (STAGE_E * 2);
        const int k0 = ch * KCH;
        #pragma unroll
        for (int s = 0; s < ASEG; s++) {
            int idx = tid * ASEG + s;       // over MTILE*4 segments
            int row = idx >> 2;
            int seg = idx & 3;
            cp16(sb + (uint32_t)(row * ALD + seg * 8) * 2,
                 A + (size_t)(m0 + row) * lda + k0 + seg * 8);
        }
        #pragma unroll
        for (int s = 0; s < BSEG; s++) {
            int idx = tid * BSEG + s;
            int row = idx / (NTILE / 8);
            int seg = idx % (NTILE / 8);
            cp16(sb + (uint32_t)(A_PL + row * BLD + seg * 8) * 2,
                 B + (size_t)(k0 + row) * ldb + n0 + seg * 8);
        }
    };

    load_stage(0, 0); CP_COMMIT();
    load_stage(1, 1); CP_COMMIT();

    for (int ch = 0; ch < nchunks; ch++) {
        const int stg = ch % 3;
        if (ch + 2 < nchunks) {
            load_stage((ch + 2) % 3, ch + 2);
            CP_COMMIT();
            CP_WAIT(2);
        } else if (ch + 1 < nchunks) {
            CP_WAIT(1);
        } else {
            CP_WAIT(0);
        }
        __syncthreads();

        const uint32_t sb = sm_base + (uint32_t)stg * (STAGE_E * 2);
        #pragma unroll
        for (int ks = 0; ks < 2; ks++) {
            const uint32_t kA = (uint32_t)(ks * 16) * 2;
            const uint32_t kB = (uint32_t)(ks * 16 * BLD) * 2;
            uint32_t a[2][4], b[NI][2];
            #pragma unroll
            for (int mi = 0; mi < 2; mi++) {
                uint32_t off = (uint32_t)(mi * 16 * ALD) * 2 + kA;
                ldsm4(a[mi][0], a[mi][1], a[mi][2], a[mi][3], sb + aOff + off);
            }
            #pragma unroll
            for (int np = 0; np < NI / 2; np++) {
                uint32_t off = kB + (uint32_t)(np * 16) * 2;
                ldsm4t(b[np * 2][0], b[np * 2][1], b[np * 2 + 1][0], b[np * 2 + 1][1],
                       sb + bOff + off);
            }
            #pragma unroll
            for (int mi = 0; mi < 2; mi++)
                #pragma unroll
                for (int ni = 0; ni < NI; ni++)
                    mma16816(acc[mi][ni], a[mi], b[ni]);
        }
        __syncthreads();
    }

    const int cr = lane >> 2;
    const int cc = (lane & 3) * 2;
    #pragma unroll
    for (int mi = 0; mi < 2; mi++)
        #pragma unroll
        for (int ni = 0; ni < NI; ni++) {
            int row = m0 + mw + mi * 16 + cr;
            int col = n0 + nw + ni * 8 + cc;
            if (Cf) {
                *reinterpret_cast<float2*>(Cf + (size_t)row * ldc + col) =
                    make_float2(acc[mi][ni][0], acc[mi][ni][1]);
                *reinterpret_cast<float2*>(Cf + (size_t)(row + 8) * ldc + col) =
                    make_float2(acc[mi][ni][2], acc[mi][ni][3]);
            }
            if (Ch) {
                *reinterpret_cast<uint32_t*>(Ch + (size_t)row * ldh + col) =
                    pack_h2(acc[mi][ni][0], acc[mi][ni][1]);
                *reinterpret_cast<uint32_t*>(Ch + (size_t)(row + 8) * ldh + col) =
                    pack_h2(acc[mi][ni][2], acc[mi][ni][3]);
            }
        }
}

#define GEMM_SMEM(MT, NT) (3 * ((MT) * ALD + KCH * ((NT) + 8)) * 2)

// ---------------- RoPE ----------------
__global__ void rope_kernel()
{
    const int row  = blockIdx.x;
    const int pos  = row & (SEQ - 1);
    const int warp = threadIdx.x >> 5;
    const int lane = threadIdx.x & 31;

    float theta = __powf(10000.0f, -(float)lane * (1.0f / 32.0f));
    float ang = (float)pos * theta;
    float s, c;
    sincosf(ang, &s, &c);

    if (warp < 16) {
        size_t off = (size_t)row * 3072 + warp * 192 + 128 + 2 * lane;
        uint32_t hv = *reinterpret_cast<uint32_t*>(g_qh + off);
        __half2 h2 = *reinterpret_cast<__half2*>(&hv);
        float x1 = __half2float(h2.x);
        float x2 = __half2float(h2.y);
        *reinterpret_cast<uint32_t*>(g_qh + off) =
            pack_h2(x1 * c - x2 * s, x1 * s + x2 * c);
    } else {
        size_t off = (size_t)row * 576 + 512 + 2 * lane;
        uint32_t hv = *reinterpret_cast<uint32_t*>(g_ckvh + off);
        __half2 h2 = *reinterpret_cast<__half2*>(&hv);
        float x1 = __half2float(h2.x);
        float x2 = __half2float(h2.y);
        *reinterpret_cast<uint32_t*>(g_peh + (size_t)row * 64 + 2 * lane) =
            pack_h2(x1 * c - x2 * s, x1 * s + x2 * c);
    }
}

// ================= HMMA fp16 flash attention, KT=64, 3-stage =================
#define QT 128
#define KT 64
#define QLD 200
#define KLD 200
#define VLD 136
#define AQ 0
#define AK (QT * QLD)
#define K_STG (KT * KLD)
#define AV (AK + 3 * K_STG)
#define V_STG (KT * VLD)
#define ATT_E (AV + 3 * V_STG)
#define ATT_SMEM (ATT_E * 2)                 // 180224 bytes

__global__ __launch_bounds__(256, 1) void attn_hmma()
{
    extern __shared__ __half sm[];
    const int tid = threadIdx.x, wid = tid >> 5, lane = tid & 31;
    const int b = blockIdx.z, h = blockIdx.y;
    const int q0 = blockIdx.x * QT;
    const uint32_t sb = smem_u32(sm);
    const float scale = 0.07216878364870323f;   // 1/sqrt(192)

    {
        int r = tid >> 1;
        const __half* src = g_qh + (size_t)(b * SEQ + q0 + r) * 3072 + h * 192;
        uint32_t dst = sb + (uint32_t)(AQ + r * QLD) * 2;
        #pragma unroll
        for (int s = 0; s < 12; s++) {
            int seg = (tid & 1) * 12 + s;
            cp16(dst + seg * 16, src + seg * 8);
        }
    }

    auto load_kv = [&](int stg, int kt0) {
        int r = tid >> 2;
        size_t row = (size_t)(b * SEQ + kt0 + r);
        const __half* kn = g_kvh + row * 4096 + h * 256;
        const __half* pe = g_peh + row * 64;
        uint32_t kd = sb + (uint32_t)(AK + stg * K_STG + r * KLD) * 2;
        uint32_t vd = sb + (uint32_t)(AV + stg * V_STG + r * VLD) * 2;
        #pragma unroll
        for (int s = 0; s < 10; s++) {
            int seg = (tid & 3) * 10 + s;
            if (seg < 16)      cp16(kd + seg * 16, kn + seg * 8);
            else if (seg < 24) cp16(kd + seg * 16, pe + (seg - 16) * 8);
            else               cp16(vd + (seg - 24) * 16, kn + 128 + (seg - 24) * 8);
        }
    };

    const int ntiles = q0 / KT + QT / KT;
    load_kv(0, 0); CP_COMMIT();
    load_kv(1, KT); CP_COMMIT();

    float m0 = -INFINITY, m1 = -INFINITY, l0 = 0.f, l1 = 0.f;
    float O[16][4];
    #pragma unroll
    for (int od = 0; od < 16; od++)
        #pragma unroll
        for (int e = 0; e < 4; e++) O[od][e] = 0.f;

    const uint32_t qb = sb + (uint32_t)(AQ + (wid * 16 + (lane & 15)) * QLD + (lane >> 4) * 8) * 2;

    for (int t = 0; t < ntiles; t++) {
        const int stg = t % 3;
        if (t + 2 < ntiles) {
            load_kv((t + 2) % 3, (t + 2) * KT);
            CP_COMMIT();
            CP_WAIT(2);
        } else if (t + 1 < ntiles) {
            CP_WAIT(1);
        } else {
            CP_WAIT(0);
        }
        __syncthreads();

        float S[8][4];
        #pragma unroll
        for (int g = 0; g < 8; g++)
            #pragma unroll
            for (int e = 0; e < 4; e++) S[g][e] = 0.f;

        const uint32_t kb = sb + (uint32_t)(AK + stg * K_STG + (lane & 15) * KLD + (lane >> 4) * 8) * 2;
        #pragma unroll
        for (int ks = 0; ks < 12; ks++) {
            uint32_t a[4];
            ldsm4(a[0], a[1], a[2], a[3], qb + ks * 32);
            #pragma unroll
            for (int np = 0; np < 4; np++) {
                uint32_t off = (uint32_t)(np * 16 * KLD) * 2 + ks * 32;
                uint32_t h0, h1, h2, h3;
                ldsm4(h0, h1, h2, h3, kb + off);
                uint32_t b0[2] = {h0, h2}, b1[2] = {h1, h3};
                mma16816(S[np * 2],     a, b0);
                mma16816(S[np * 2 + 1], a, b1);
            }
        }

        const int mrow0 = q0 + wid * 16 + (lane >> 2);
        const int kcol0 = t * KT + (lane & 3) * 2;
        const bool needmask = (t * KT + KT - 1) > (q0 + wid * 16);
        if (needmask) {
            #pragma unroll
            for (int g = 0; g < 8; g++) {
                int kc = kcol0 + g * 8;
                S[g][0] = (kc     <= mrow0)     ? S[g][0] * scale : -INFINITY;
                S[g][1] = (kc + 1 <= mrow0)     ? S[g][1] * scale : -INFINITY;
                S[g][2] = (kc     <= mrow0 + 8) ? S[g][2] * scale : -INFINITY;
                S[g][3] = (kc + 1 <= mrow0 + 8) ? S[g][3] * scale : -INFINITY;
            }
        } else {
            #pragma unroll
            for (int g = 0; g < 8; g++)
                #pragma unroll
                for (int e = 0; e < 4; e++) S[g][e] *= scale;
        }

        float tm0 = -INFINITY, tm1 = -INFINITY;
        #pragma unroll
        for (int g = 0; g < 8; g++) {
            tm0 = fmaxf(tm0, fmaxf(S[g][0], S[g][1]));
            tm1 = fmaxf(tm1, fmaxf(S[g][2], S[g][3]));
        }
        tm0 = fmaxf(tm0, __shfl_xor_sync(0xffffffffu, tm0, 1));
        tm0 = fmaxf(tm0, __shfl_xor_sync(0xffffffffu, tm0, 2));
        tm1 = fmaxf(tm1, __shfl_xor_sync(0xffffffffu, tm1, 1));
        tm1 = fmaxf(tm1, __shfl_xor_sync(0xffffffffu, tm1, 2));

        float mn0 = fmaxf(m0, tm0), mn1 = fmaxf(m1, tm1);
        float al0 = __expf(m0 - mn0), al1 = __expf(m1 - mn1);
        m0 = mn0; m1 = mn1;

        float P[8][4];
        float s0 = 0.f, s1 = 0.f;
        #pragma unroll
        for (int g = 0; g < 8; g++) {
            P[g][0] = __expf(S[g][0] - m0); s0 += P[g][0];
            P[g][1] = __expf(S[g][1] - m0); s0 += P[g][1];
            P[g][2] = __expf(S[g][2] - m1); s1 += P[g][2];
            P[g][3] = __expf(S[g][3] - m1); s1 += P[g][3];
        }
        s0 += __shfl_xor_sync(0xffffffffu, s0, 1);
        s0 += __shfl_xor_sync(0xffffffffu, s0, 2);
        s1 += __shfl_xor_sync(0xffffffffu, s1, 1);
        s1 += __shfl_xor_sync(0xffffffffu, s1, 2);
        l0 = l0 * al0 + s0;
        l1 = l1 * al1 + s1;

        #pragma unroll
        for (int od = 0; od < 16; od++) {
            O[od][0] *= al0; O[od][1] *= al0;
            O[od][2] *= al1; O[od][3] *= al1;
        }

        uint32_t aP[4][4];
        #pragma unroll
        for (int kp = 0; kp < 4; kp++) {
            #pragma unroll
            for (int rr = 0; rr < 2; rr++) {
                #pragma unroll
                for (int hh = 0; hh < 2; hh++) {
                    aP[kp][hh * 2 + rr] = pack_h2(P[2 * kp + hh][rr * 2 + 0],
                                                  P[2 * kp + hh][rr * 2 + 1]);
                }
            }
        }

        const uint32_t vb = sb + (uint32_t)(AV + stg * V_STG + (lane & 15) * VLD + (lane >> 4) * 8) * 2;
        #pragma unroll
        for (int kp = 0; kp < 4; kp++) {
            const uint32_t vk = vb + (uint32_t)(kp * 16 * VLD) * 2;
            #pragma unroll
            for (int od2 = 0; od2 < 8; od2++) {
                uint32_t bv[4];
                ldsm4t(bv[0], bv[1], bv[2], bv[3], vk + od2 * 32);
                mma16816(O[od2 * 2],     aP[kp], bv);
                mma16816(O[od2 * 2 + 1], aP[kp], bv + 2);
            }
        }
        __syncthreads();
    }

    float inv0 = 1.f / l0, inv1 = 1.f / l1;
    int row0 = b * SEQ + q0 + wid * 16 + (lane >> 2);
    size_t o0 = (size_t)row0 * 2048 + h * 128 + (lane & 3) * 2;
    size_t o1 = (size_t)(row0 + 8) * 2048 + h * 128 + (lane & 3) * 2;
    #pragma unroll
    for (int od = 0; od < 16; od++) {
        *reinterpret_cast<uint32_t*>(g_ah + o0 + od * 8) =
            pack_h2(O[od][0] * inv0, O[od][1] * inv0);
        *reinterpret_cast<uint32_t*>(g_ah + o1 + od * 8) =
            pack_h2(O[od][2] * inv1, O[od][3] * inv1);
    }
}

// ---------------- launch ----------------
extern "C" void kernel_launch(void* const* d_in, const int* in_sizes, int n_in,
                              void* d_out, int out_size)
{
    const float* x    = (const float*)d_in[0];
    const float* Wqa  = (const float*)d_in[1];
    const float* Wqb  = (const float*)d_in[2];
    const float* Wkva = (const float*)d_in[3];
    const float* Wkvb = (const float*)d_in[4];
    const float* Wout = (const float*)d_in[5];
    float* out = (float*)d_out;

    __half *xh, *q1h, *ckvh, *qh, *kvh, *ah;
    __half *wqah, *wqbh, *wkvah, *wkvbh, *wouth;
    cudaGetSymbolAddress((void**)&xh,   g_xh);
    cudaGetSymbolAddress((void**)&q1h,  g_q1h);
    cudaGetSymbolAddress((void**)&ckvh, g_ckvh);
    cudaGetSymbolAddress((void**)&qh,   g_qh);
    cudaGetSymbolAddress((void**)&kvh,  g_kvh);
    cudaGetSymbolAddress((void**)&ah,   g_ah);
    cudaGetSymbolAddress((void**)&wqah, g_Wqah);
    cudaGetSymbolAddress((void**)&wqbh, g_Wqbh);
    cudaGetSymbolAddress((void**)&wkvah, g_Wkvah);
    cudaGetSymbolAddress((void**)&wkvbh, g_Wkvbh);
    cudaGetSymbolAddress((void**)&wouth, g_Wouth);

    cudaFuncSetAttribute((const void*)gemm_hmma<128, 128>,
                         cudaFuncAttributeMaxDynamicSharedMemorySize, GEMM_SMEM(128, 128));
    cudaFuncSetAttribute((const void*)gemm_hmma<64, 128>,
                         cudaFuncAttributeMaxDynamicSharedMemorySize, GEMM_SMEM(64, 128));
    cudaFuncSetAttribute((const void*)gemm_hmma<64, 64>,
                         cudaFuncAttributeMaxDynamicSharedMemorySize, GEMM_SMEM(64, 64));
    cudaFuncSetAttribute((const void*)attn_hmma,
                         cudaFuncAttributeMaxDynamicSharedMemorySize, ATT_SMEM);

    dim3 t(256);

    // fused input conversions (x + 5 weights), one launch
    conv6<<<(C6 + 255) / 256, t>>>(x, Wqa, Wqb, Wkva, Wkvb, Wout);

    // q1 = x @ Wqa  (M64 tiles: 256 CTAs)
    gemm_hmma<64, 128><<<dim3(4, 64),  t, GEMM_SMEM(64, 128)>>>(
        xh, 2048, wqah, 512, nullptr, 0, q1h, 512, 64);
    // q = q1 @ Wqb
    gemm_hmma<128, 128><<<dim3(24, 32), t, GEMM_SMEM(128, 128)>>>(
        q1h, 512, wqbh, 3072, nullptr, 0, qh, 3072, 16);
    // ckv = x @ Wkva (M64 wide + narrow tail)
    gemm_hmma<64, 128><<<dim3(4, 64), t, GEMM_SMEM(64, 128)>>>(
        xh, 2048, wkvah, 576, nullptr, 0, ckvh, 576, 64);
    gemm_hmma<64, 64><<<dim3(1, 64),  t, GEMM_SMEM(64, 64)>>>(
        xh, 2048, wkvah + 512, 576, nullptr, 0, ckvh + 512, 576, 64);
    // rope (q_pe in place; k_pe -> pe plane)
    rope_kernel<<<4096, 544>>>();
    // kv = ckv[:, :512] @ Wkvb
    gemm_hmma<128, 128><<<dim3(32, 32), t, GEMM_SMEM(128, 128)>>>(
        ckvh, 576, wkvbh, 4096, nullptr, 0, kvh, 4096, 16);
    // flash attention
    attn_hmma<<<dim3(SEQ / QT, NHEADS, 2), 256, ATT_SMEM>>>();
    // out = att @ Wout -> fp32
    gemm_hmma<128, 128><<<dim3(16, 32), t, GEMM_SMEM(128, 128)>>>(
        ah, 2048, wouth, 2048, out, 2048, nullptr, 0, 64);
}